// round 1
// baseline (speedup 1.0000x reference)
#include <cuda_runtime.h>
#include <math.h>

#define BATCH 2048
#define NP    32
#define DD    6
#define NOBS  17
#define HID   256
#define NSTEPS 10
#define LRATE 0.1f
#define CLIP_LIM 1.0f
// np.float32(np.log(33.0))
#define LOG_NP1 3.49650756f

// W2 transposed scratch (allocation-free: __device__ global)
__device__ float g_W2T[HID * HID];

// ---------------------------------------------------------------------------
// One-time (per launch) transpose of W2 so the backward matmul has coalesced
// weight loads. grid (8,8), block (32,8).
// ---------------------------------------------------------------------------
__global__ void transposeW2_kernel(const float* __restrict__ W2) {
    __shared__ float tile[32][33];
    int bx = blockIdx.x, by = blockIdx.y;
    int x = bx * 32 + threadIdx.x;
#pragma unroll
    for (int i = 0; i < 32; i += 8) {
        int y = by * 32 + threadIdx.y + i;
        tile[threadIdx.y + i][threadIdx.x] = W2[y * HID + x];
    }
    __syncthreads();
    int xo = by * 32 + threadIdx.x;
#pragma unroll
    for (int i = 0; i < 32; i += 8) {
        int yo = bx * 32 + threadIdx.y + i;
        g_W2T[yo * HID + xo] = tile[threadIdx.x][threadIdx.y + i];
    }
}

// ---------------------------------------------------------------------------
// Main persistent-per-batch kernel. One block = one batch of 32 particles,
// runs all 10 SVGD steps in shared memory.
// ---------------------------------------------------------------------------
struct __align__(16) Smem {
    float W1[23 * HID];     // 23x256 weights (rows 17..22 are the X part)
    float b1[HID];
    float b2[HID];
    float W3[HID];
    float obs[NP * NOBS];   // 32x17
    float X[2][NP * DD];    // ping-pong particle positions
    float s[NP * DD];       // scores
    float h1[NP * HID];     // relu(z1), later overwritten with dz1
    float dz2[NP * HID];    // mask2 * W3
    float dsq[NP * NP];     // pairwise squared distances
    float sortbuf[NP * NP]; // bitonic sort workspace
    float logp[NP];
    float gamma;
};

extern __shared__ float smem_raw[];

__global__ void __launch_bounds__(256, 2) svgd_kernel(
    const float* __restrict__ g_obs, const float* __restrict__ g_a,
    const float* __restrict__ g_W1, const float* __restrict__ g_b1,
    const float* __restrict__ g_W2, const float* __restrict__ g_b2,
    const float* __restrict__ g_W3, float* __restrict__ g_out)
{
    Smem* sm = reinterpret_cast<Smem*>(smem_raw);
    const int tid = threadIdx.x;
    const int b = blockIdx.x;
    const int warp = tid >> 5;
    const int lane = tid & 31;

    // ---- one-time loads --------------------------------------------------
    for (int i = tid; i < 23 * HID; i += 256) sm->W1[i] = g_W1[i];
    sm->b1[tid] = g_b1[tid];
    sm->b2[tid] = g_b2[tid];
    sm->W3[tid] = g_W3[tid];
    for (int i = tid; i < NP * NOBS; i += 256) sm->obs[i] = g_obs[b * NP * NOBS + i];
    for (int i = tid; i < NP * DD; i += 256)   sm->X[0][i] = g_a[b * NP * DD + i];
    if (tid < NP) sm->logp[tid] = 0.0f;
    __syncthreads();

    int cur = 0;
    for (int step = 0; step < NSTEPS; step++) {
        const float* X = sm->X[cur];

        // ---- z1 = relu(x @ W1 + b1), thread owns column h=tid -----------
        {
            const int h = tid;
            for (int r = 0; r < NP; r++) {
                float z = sm->b1[h];
#pragma unroll
                for (int k = 0; k < NOBS; k++)
                    z = fmaf(sm->obs[r * NOBS + k], sm->W1[k * HID + h], z);
#pragma unroll
                for (int d = 0; d < DD; d++)
                    z = fmaf(X[r * DD + d], sm->W1[(NOBS + d) * HID + h], z);
                sm->h1[r * HID + h] = fmaxf(z, 0.0f);
            }
        }
        __syncthreads();

        // ---- z2 = h1 @ W2 + b2 ; dz2 = (z2>0) * W3 ----------------------
        {
            const int h = tid;
            float acc[NP];
#pragma unroll
            for (int r = 0; r < NP; r++) acc[r] = sm->b2[h];
            for (int kc = 0; kc < HID; kc += 8) {
                float w[8];
#pragma unroll
                for (int j = 0; j < 8; j++) w[j] = g_W2[(kc + j) * HID + h];
#pragma unroll
                for (int r = 0; r < NP; r++) {
                    float4 a0 = *reinterpret_cast<const float4*>(&sm->h1[r * HID + kc]);
                    float4 a1 = *reinterpret_cast<const float4*>(&sm->h1[r * HID + kc + 4]);
                    float t = acc[r];
                    t = fmaf(a0.x, w[0], t); t = fmaf(a0.y, w[1], t);
                    t = fmaf(a0.z, w[2], t); t = fmaf(a0.w, w[3], t);
                    t = fmaf(a1.x, w[4], t); t = fmaf(a1.y, w[5], t);
                    t = fmaf(a1.z, w[6], t); t = fmaf(a1.w, w[7], t);
                    acc[r] = t;
                }
            }
            const float w3 = sm->W3[h];
#pragma unroll
            for (int r = 0; r < NP; r++)
                sm->dz2[r * HID + h] = (acc[r] > 0.0f) ? w3 : 0.0f;
        }
        __syncthreads();

        // ---- dz1 = (h1>0) * (dz2 @ W2^T), stored back into h1 -----------
        {
            const int h = tid;
            float acc[NP];
#pragma unroll
            for (int r = 0; r < NP; r++) acc[r] = 0.0f;
            for (int kc = 0; kc < HID; kc += 8) {
                float w[8];
#pragma unroll
                for (int j = 0; j < 8; j++) w[j] = g_W2T[(kc + j) * HID + h];
#pragma unroll
                for (int r = 0; r < NP; r++) {
                    float4 a0 = *reinterpret_cast<const float4*>(&sm->dz2[r * HID + kc]);
                    float4 a1 = *reinterpret_cast<const float4*>(&sm->dz2[r * HID + kc + 4]);
                    float t = acc[r];
                    t = fmaf(a0.x, w[0], t); t = fmaf(a0.y, w[1], t);
                    t = fmaf(a0.z, w[2], t); t = fmaf(a0.w, w[3], t);
                    t = fmaf(a1.x, w[4], t); t = fmaf(a1.y, w[5], t);
                    t = fmaf(a1.z, w[6], t); t = fmaf(a1.w, w[7], t);
                    acc[r] = t;
                }
            }
#pragma unroll
            for (int r = 0; r < NP; r++) {
                float m = sm->h1[r * HID + h];
                sm->h1[r * HID + h] = (m > 0.0f) ? acc[r] : 0.0f;
            }
        }
        __syncthreads();

        // ---- score = dz1 @ W1[17:23,:]^T  (warp per 4 rows) -------------
        {
            for (int r = warp * 4; r < warp * 4 + 4; r++) {
                float dz[8];
#pragma unroll
                for (int i = 0; i < 8; i++)
                    dz[i] = sm->h1[r * HID + lane + 32 * i];
                float p[DD];
#pragma unroll
                for (int d = 0; d < DD; d++) {
                    float t = 0.0f;
#pragma unroll
                    for (int i = 0; i < 8; i++)
                        t = fmaf(dz[i], sm->W1[(NOBS + d) * HID + lane + 32 * i], t);
#pragma unroll
                    for (int off = 16; off > 0; off >>= 1)
                        t += __shfl_xor_sync(0xFFFFFFFFu, t, off);
                    p[d] = t;
                }
                if (lane == 0) {
#pragma unroll
                    for (int d = 0; d < DD; d++) sm->s[r * DD + d] = p[d];
                }
            }
        }
        __syncthreads();

        // ---- pairwise squared distances ---------------------------------
        for (int p = tid; p < NP * NP; p += 256) {
            const int i = p >> 5, j = p & 31;
            float dsq = 0.0f;
#pragma unroll
            for (int d = 0; d < DD; d++) {
                float dx = X[i * DD + d] - X[j * DD + d];
                dsq = fmaf(dx, dx, dsq);
            }
            sm->dsq[p] = dsq;
            sm->sortbuf[p] = dsq;
        }
        __syncthreads();

        // ---- exact median via bitonic sort of 1024 values ---------------
        for (int k = 2; k <= NP * NP; k <<= 1) {
            for (int j = k >> 1; j > 0; j >>= 1) {
                for (int t = tid; t < NP * NP; t += 256) {
                    const int ixj = t ^ j;
                    if (ixj > t) {
                        float v0 = sm->sortbuf[t];
                        float v1 = sm->sortbuf[ixj];
                        const bool up = (t & k) == 0;
                        if ((v0 > v1) == up) {
                            sm->sortbuf[t] = v1;
                            sm->sortbuf[ixj] = v0;
                        }
                    }
                }
                __syncthreads();
            }
        }
        if (tid == 0) {
            const float med = sm->sortbuf[(NP * NP - 1) / 2];
            const float h = med / (2.0f * LOG_NP1);
            sm->gamma = 1.0f / (1e-8f + 2.0f * h);
        }
        __syncthreads();

        // ---- RBF phi / logp update (warp per 4 rows) --------------------
        {
            const float gamma = sm->gamma;
            const int nxt = cur ^ 1;
            for (int i = warp * 4; i < warp * 4 + 4; i++) {
                const int j = lane;
                float dx[DD];
#pragma unroll
                for (int d = 0; d < DD; d++)
                    dx[d] = X[i * DD + d] - X[j * DD + d];
                const float dsq = sm->dsq[i * NP + j];
                const float kap = __expf(-gamma * dsq) ; // fast exp has ~2^-21 rel err
                float red[8];
                float ds = 0.0f;
#pragma unroll
                for (int d = 0; d < DD; d++) {
                    red[d] = kap * (sm->s[j * DD + d] + 2.0f * gamma * dx[d]);
                    ds = fmaf(dx[d], sm->s[j * DD + d], ds);
                }
                red[6] = -2.0f * gamma * kap * ds;                       // line_4 term
                red[7] = 2.0f * gamma * dsq * kap - (float)DD * kap;     // line_5 inner
#pragma unroll
                for (int q = 0; q < 8; q++) {
#pragma unroll
                    for (int off = 16; off > 0; off >>= 1)
                        red[q] += __shfl_xor_sync(0xFFFFFFFFu, red[q], off);
                }
                if (lane == 0) {
#pragma unroll
                    for (int d = 0; d < DD; d++) {
                        const float phi = red[d] * (1.0f / (float)NP);
                        float xn = X[i * DD + d] + LRATE * phi;
                        xn = fminf(fmaxf(xn, -CLIP_LIM), CLIP_LIM);
                        sm->X[nxt][i * DD + d] = xn;
                    }
                    const float l4 = red[6] * (1.0f / (float)NP);
                    const float l5 = -2.0f * gamma * (red[7] * (1.0f / (float)NP));
                    sm->logp[i] -= LRATE * (l4 + l5);
                }
            }
        }
        cur ^= 1;
        __syncthreads();
    }

    // ---- write outputs: a (B*N*D) then logp (B*N) ------------------------
    for (int i = tid; i < NP * DD; i += 256)
        g_out[b * (NP * DD) + i] = sm->X[cur][i];
    if (tid < NP)
        g_out[BATCH * NP * DD + b * NP + tid] = sm->logp[tid];
}

// ---------------------------------------------------------------------------
extern "C" void kernel_launch(void* const* d_in, const int* in_sizes, int n_in,
                              void* d_out, int out_size) {
    const float* obs = (const float*)d_in[0];
    const float* a   = (const float*)d_in[1];
    const float* W1  = (const float*)d_in[2];
    const float* b1  = (const float*)d_in[3];
    const float* W2  = (const float*)d_in[4];
    const float* b2  = (const float*)d_in[5];
    const float* W3  = (const float*)d_in[6];
    // d_in[7] = b3: does not affect the gradient or outputs — unused.
    float* out = (float*)d_out;

    transposeW2_kernel<<<dim3(8, 8), dim3(32, 8)>>>(W2);

    cudaFuncSetAttribute(svgd_kernel,
                         cudaFuncAttributeMaxDynamicSharedMemorySize,
                         (int)sizeof(Smem));
    svgd_kernel<<<BATCH, 256, sizeof(Smem)>>>(obs, a, W1, b1, W2, b2, W3, out);
}

// round 2
// speedup vs baseline: 1.0181x; 1.0181x over previous
#include <cuda_runtime.h>
#include <math.h>

#define BATCH 2048
#define NP    32
#define DD    6
#define NOBS  17
#define HID   256
#define NSTEPS 10
#define LRATE 0.1f
#define CLIP_LIM 1.0f
// np.float32(np.log(33.0))
#define LOG_NP1 3.49650756f

// W2 transposed scratch (allocation-free: __device__ global)
__device__ float g_W2T[HID * HID];

// ---------------------------------------------------------------------------
// packed f32x2 helpers (Blackwell FFMA2 via PTX)
// ---------------------------------------------------------------------------
__device__ __forceinline__ unsigned long long splat2(float a) {
    unsigned long long r;
    asm("mov.b64 %0, {%1, %1};" : "=l"(r) : "f"(a));
    return r;
}
__device__ __forceinline__ void ffma2(unsigned long long& d,
                                      unsigned long long a,
                                      unsigned long long b) {
    asm("fma.rn.f32x2 %0, %1, %2, %0;" : "+l"(d) : "l"(a), "l"(b));
}
__device__ __forceinline__ float2 unpack2(unsigned long long v) {
    float2 f;
    asm("mov.b64 {%0, %1}, %2;" : "=f"(f.x), "=f"(f.y) : "l"(v));
    return f;
}

// ---------------------------------------------------------------------------
// One-time transpose of W2 so the backward matmul has coalesced weight loads.
// ---------------------------------------------------------------------------
__global__ void transposeW2_kernel(const float* __restrict__ W2) {
    __shared__ float tile[32][33];
    int bx = blockIdx.x, by = blockIdx.y;
    int x = bx * 32 + threadIdx.x;
#pragma unroll
    for (int i = 0; i < 32; i += 8) {
        int y = by * 32 + threadIdx.y + i;
        tile[threadIdx.y + i][threadIdx.x] = W2[y * HID + x];
    }
    __syncthreads();
    int xo = by * 32 + threadIdx.x;
#pragma unroll
    for (int i = 0; i < 32; i += 8) {
        int yo = bx * 32 + threadIdx.y + i;
        g_W2T[yo * HID + xo] = tile[threadIdx.x][threadIdx.y + i];
    }
}

// ---------------------------------------------------------------------------
struct __align__(16) Smem {
    float W1[23 * HID];
    float b1[HID];
    float b2[HID];
    float W3[HID];
    float obs[NP * NOBS];
    float X[2][NP * DD];
    float s[NP * DD];
    float h1[NP * HID];     // relu(z1), later overwritten with dz1
    float dz2[NP * HID];    // mask2 * W3
    float dsq[NP * NP];
    float sortbuf[512];     // upper-triangle (496) + inf pad
    float logp[NP];
    float gamma;
};

extern __shared__ float smem_raw[];

// ---------------------------------------------------------------------------
// Register-blocked packed matmul: 32x256 (rows x cols), K=256.
// A in shared (row-major), B in global (row-major [k][col]).
// Each thread: 4 rows (rg=tid>>5), 8 cols (cg=tid&31), acc packed over col
// pairs. Epilogue handled by caller via the acc array.
// ---------------------------------------------------------------------------
__device__ __forceinline__ void mm_block(const float* __restrict__ A,
                                         const float* __restrict__ B,
                                         int r0, int c0,
                                         unsigned long long acc[16]) {
#pragma unroll
    for (int i = 0; i < 16; i++) acc[i] = 0ull;
    const float* a0 = A + r0 * HID;
#pragma unroll 2
    for (int k = 0; k < HID; k++) {
        const ulonglong2 wA = *reinterpret_cast<const ulonglong2*>(B + k * HID + c0);
        const ulonglong2 wB = *reinterpret_cast<const ulonglong2*>(B + k * HID + c0 + 4);
#pragma unroll
        for (int r = 0; r < 4; r++) {
            unsigned long long ap = splat2(a0[r * HID + k]);
            ffma2(acc[r * 4 + 0], ap, wA.x);
            ffma2(acc[r * 4 + 1], ap, wA.y);
            ffma2(acc[r * 4 + 2], ap, wB.x);
            ffma2(acc[r * 4 + 3], ap, wB.y);
        }
    }
}

__global__ void __launch_bounds__(256, 2) svgd_kernel(
    const float* __restrict__ g_obs, const float* __restrict__ g_a,
    const float* __restrict__ g_W1, const float* __restrict__ g_b1,
    const float* __restrict__ g_W2, const float* __restrict__ g_b2,
    const float* __restrict__ g_W3, float* __restrict__ g_out)
{
    Smem* sm = reinterpret_cast<Smem*>(smem_raw);
    const int tid = threadIdx.x;
    const int b = blockIdx.x;
    const int warp = tid >> 5;
    const int lane = tid & 31;
    const int r0 = (tid >> 5) * 4;   // row group for blocked matmuls
    const int c0 = (tid & 31) * 8;   // col group

    // ---- one-time loads --------------------------------------------------
    for (int i = tid; i < 23 * HID; i += 256) sm->W1[i] = g_W1[i];
    sm->b1[tid] = g_b1[tid];
    sm->b2[tid] = g_b2[tid];
    sm->W3[tid] = g_W3[tid];
    for (int i = tid; i < NP * NOBS; i += 256) sm->obs[i] = g_obs[b * NP * NOBS + i];
    for (int i = tid; i < NP * DD; i += 256)   sm->X[0][i] = g_a[b * NP * DD + i];
    if (tid < NP) sm->logp[tid] = 0.0f;
    __syncthreads();

    int cur = 0;
    for (int step = 0; step < NSTEPS; step++) {
        const float* X = sm->X[cur];

        // ---- z1 = relu(x @ W1 + b1), thread owns column h=tid -----------
        {
            const int h = tid;
            for (int r = 0; r < NP; r++) {
                float z = sm->b1[h];
#pragma unroll
                for (int k = 0; k < NOBS; k++)
                    z = fmaf(sm->obs[r * NOBS + k], sm->W1[k * HID + h], z);
#pragma unroll
                for (int d = 0; d < DD; d++)
                    z = fmaf(X[r * DD + d], sm->W1[(NOBS + d) * HID + h], z);
                sm->h1[r * HID + h] = fmaxf(z, 0.0f);
            }
        }
        __syncthreads();

        // ---- z2 = h1 @ W2 + b2 ; dz2 = (z2>0) * W3 ----------------------
        {
            unsigned long long acc[16];
            mm_block(sm->h1, g_W2, r0, c0, acc);
#pragma unroll
            for (int r = 0; r < 4; r++) {
#pragma unroll
                for (int cp = 0; cp < 4; cp++) {
                    const int c = c0 + 2 * cp;
                    float2 z = unpack2(acc[r * 4 + cp]);
                    z.x += sm->b2[c];
                    z.y += sm->b2[c + 1];
                    float2 o;
                    o.x = (z.x > 0.0f) ? sm->W3[c]     : 0.0f;
                    o.y = (z.y > 0.0f) ? sm->W3[c + 1] : 0.0f;
                    *reinterpret_cast<float2*>(&sm->dz2[(r0 + r) * HID + c]) = o;
                }
            }
        }
        __syncthreads();

        // ---- dz1 = (h1>0) * (dz2 @ W2^T), stored back into h1 -----------
        {
            unsigned long long acc[16];
            mm_block(sm->dz2, g_W2T, r0, c0, acc);
#pragma unroll
            for (int r = 0; r < 4; r++) {
#pragma unroll
                for (int cp = 0; cp < 4; cp++) {
                    const int c = c0 + 2 * cp;
                    float2 v = unpack2(acc[r * 4 + cp]);
                    float2 m = *reinterpret_cast<const float2*>(&sm->h1[(r0 + r) * HID + c]);
                    float2 o;
                    o.x = (m.x > 0.0f) ? v.x : 0.0f;
                    o.y = (m.y > 0.0f) ? v.y : 0.0f;
                    *reinterpret_cast<float2*>(&sm->h1[(r0 + r) * HID + c]) = o;
                }
            }
        }
        __syncthreads();

        // ---- score = dz1 @ W1[17:23,:]^T  (warp per 4 rows) -------------
        {
            for (int r = warp * 4; r < warp * 4 + 4; r++) {
                float dz[8];
#pragma unroll
                for (int i = 0; i < 8; i++)
                    dz[i] = sm->h1[r * HID + lane + 32 * i];
                float p[DD];
#pragma unroll
                for (int d = 0; d < DD; d++) {
                    float t = 0.0f;
#pragma unroll
                    for (int i = 0; i < 8; i++)
                        t = fmaf(dz[i], sm->W1[(NOBS + d) * HID + lane + 32 * i], t);
#pragma unroll
                    for (int off = 16; off > 0; off >>= 1)
                        t += __shfl_xor_sync(0xFFFFFFFFu, t, off);
                    p[d] = t;
                }
                if (lane == 0) {
#pragma unroll
                    for (int d = 0; d < DD; d++) sm->s[r * DD + d] = p[d];
                }
            }
        }
        __syncthreads();

        // ---- pairwise squared distances + upper-triangle extraction -----
        if (tid < 16) sm->sortbuf[496 + tid] = __int_as_float(0x7f800000);
        for (int p = tid; p < NP * NP; p += 256) {
            const int i = p >> 5, j = p & 31;
            float dsq = 0.0f;
#pragma unroll
            for (int d = 0; d < DD; d++) {
                float dx = X[i * DD + d] - X[j * DD + d];
                dsq = fmaf(dx, dx, dsq);
            }
            sm->dsq[p] = dsq;
            if (i < j) {
                // upper-triangle linear index
                const int t = i * NP - ((i * (i + 1)) >> 1) + (j - i - 1);
                sm->sortbuf[t] = dsq;
            }
        }
        __syncthreads();

        // ---- exact median: sort 512 (496 distinct pair values + inf pad).
        // Full multiset = 32 diag zeros + each pair value twice; element 511
        // of 1024 maps to element (511-32)/2 = 239 of the sorted pairs.
        for (int k = 2; k <= 512; k <<= 1) {
            for (int j = k >> 1; j > 0; j >>= 1) {
                for (int t = tid; t < 512; t += 256) {
                    const int ixj = t ^ j;
                    if (ixj > t) {
                        float v0 = sm->sortbuf[t];
                        float v1 = sm->sortbuf[ixj];
                        const bool up = (t & k) == 0;
                        if ((v0 > v1) == up) {
                            sm->sortbuf[t] = v1;
                            sm->sortbuf[ixj] = v0;
                        }
                    }
                }
                __syncthreads();
            }
        }
        if (tid == 0) {
            const float med = sm->sortbuf[239];
            const float h = med / (2.0f * LOG_NP1);
            sm->gamma = 1.0f / (1e-8f + 2.0f * h);
        }
        __syncthreads();

        // ---- RBF phi / logp update (warp per 4 rows) --------------------
        {
            const float gamma = sm->gamma;
            const int nxt = cur ^ 1;
            for (int i = warp * 4; i < warp * 4 + 4; i++) {
                const int j = lane;
                float dx[DD];
#pragma unroll
                for (int d = 0; d < DD; d++)
                    dx[d] = X[i * DD + d] - X[j * DD + d];
                const float dsq = sm->dsq[i * NP + j];
                const float kap = __expf(-gamma * dsq);
                float red[8];
                float ds = 0.0f;
#pragma unroll
                for (int d = 0; d < DD; d++) {
                    red[d] = kap * (sm->s[j * DD + d] + 2.0f * gamma * dx[d]);
                    ds = fmaf(dx[d], sm->s[j * DD + d], ds);
                }
                red[6] = -2.0f * gamma * kap * ds;                   // line_4
                red[7] = 2.0f * gamma * dsq * kap - (float)DD * kap; // line_5 inner
#pragma unroll
                for (int q = 0; q < 8; q++) {
#pragma unroll
                    for (int off = 16; off > 0; off >>= 1)
                        red[q] += __shfl_xor_sync(0xFFFFFFFFu, red[q], off);
                }
                if (lane == 0) {
#pragma unroll
                    for (int d = 0; d < DD; d++) {
                        const float phi = red[d] * (1.0f / (float)NP);
                        float xn = X[i * DD + d] + LRATE * phi;
                        xn = fminf(fmaxf(xn, -CLIP_LIM), CLIP_LIM);
                        sm->X[nxt][i * DD + d] = xn;
                    }
                    const float l4 = red[6] * (1.0f / (float)NP);
                    const float l5 = -2.0f * gamma * (red[7] * (1.0f / (float)NP));
                    sm->logp[i] -= LRATE * (l4 + l5);
                }
            }
        }
        cur ^= 1;
        __syncthreads();
    }

    // ---- write outputs: a (B*N*D) then logp (B*N) ------------------------
    for (int i = tid; i < NP * DD; i += 256)
        g_out[b * (NP * DD) + i] = sm->X[cur][i];
    if (tid < NP)
        g_out[BATCH * NP * DD + b * NP + tid] = sm->logp[tid];
}

// ---------------------------------------------------------------------------
extern "C" void kernel_launch(void* const* d_in, const int* in_sizes, int n_in,
                              void* d_out, int out_size) {
    const float* obs = (const float*)d_in[0];
    const float* a   = (const float*)d_in[1];
    const float* W1  = (const float*)d_in[2];
    const float* b1  = (const float*)d_in[3];
    const float* W2  = (const float*)d_in[4];
    const float* b2  = (const float*)d_in[5];
    const float* W3  = (const float*)d_in[6];
    // d_in[7] = b3: does not affect outputs — unused.
    float* out = (float*)d_out;

    transposeW2_kernel<<<dim3(8, 8), dim3(32, 8)>>>(W2);

    cudaFuncSetAttribute(svgd_kernel,
                         cudaFuncAttributeMaxDynamicSharedMemorySize,
                         (int)sizeof(Smem));
    svgd_kernel<<<BATCH, 256, sizeof(Smem)>>>(obs, a, W1, b1, W2, b2, W3, out);
}

// round 3
// speedup vs baseline: 1.4755x; 1.4493x over previous
#include <cuda_runtime.h>
#include <math.h>

#define BATCH 2048
#define NP    32
#define DD    6
#define NOBS  17
#define NIN   23        // OBS + D
#define HID   256
#define NSTEPS 10
#define LRATE 0.1f
#define CLIP_LIM 1.0f
// np.float32(np.log(33.0))
#define LOG_NP1 3.49650756f

// W2 transposed scratch (allocation-free: __device__ global)
__device__ __align__(256) float g_W2T[HID * HID];

// ---------------------------------------------------------------------------
// packed f32x2 helpers (Blackwell FFMA2 via PTX)
// ---------------------------------------------------------------------------
__device__ __forceinline__ unsigned long long splat2(float a) {
    unsigned long long r;
    asm("mov.b64 %0, {%1, %1};" : "=l"(r) : "f"(a));
    return r;
}
__device__ __forceinline__ void ffma2(unsigned long long& d,
                                      unsigned long long a,
                                      unsigned long long b) {
    asm("fma.rn.f32x2 %0, %1, %2, %0;" : "+l"(d) : "l"(a), "l"(b));
}
__device__ __forceinline__ float2 unpack2(unsigned long long v) {
    float2 f;
    asm("mov.b64 {%0, %1}, %2;" : "=f"(f.x), "=f"(f.y) : "l"(v));
    return f;
}

// ---------------------------------------------------------------------------
// One-time transpose of W2 (coalesced weights for the backward matmul).
// ---------------------------------------------------------------------------
__global__ void transposeW2_kernel(const float* __restrict__ W2) {
    __shared__ float tile[32][33];
    int bx = blockIdx.x, by = blockIdx.y;
    int x = bx * 32 + threadIdx.x;
#pragma unroll
    for (int i = 0; i < 32; i += 8) {
        int y = by * 32 + threadIdx.y + i;
        tile[threadIdx.y + i][threadIdx.x] = W2[y * HID + x];
    }
    __syncthreads();
    int xo = by * 32 + threadIdx.x;
#pragma unroll
    for (int i = 0; i < 32; i += 8) {
        int yo = bx * 32 + threadIdx.y + i;
        g_W2T[yo * HID + xo] = tile[threadIdx.x][threadIdx.y + i];
    }
}

// ---------------------------------------------------------------------------
// Swizzled transposed activation index: logical arr[c][r] (c = feature,
// r = particle row 0..31). Quad-granular XOR swizzle keeps quads intact
// (aligned float4 ops) while spreading bank groups across c.
// ---------------------------------------------------------------------------
__device__ __forceinline__ int atidx(int c, int r) {
    return c * 32 + (r ^ ((c & 7) << 2));
}

struct __align__(16) Smem {
    float inT[NIN * 32 + 32];   // swizzled transposed concat(obs, X), 23x32
    float hT[HID * 32];         // swizzled transposed relu(z1); later dz1
    float dT[HID * 32];         // swizzled transposed dz2
    float b1[HID];
    float b2[HID];
    float W3[HID];
    float X[2][NP * DD];        // ping-pong particle positions (row-major)
    float s[NP * DD];           // scores
    float dsq[NP * NP];
    float sortbuf[512];         // upper-triangle (496) + inf pad
    float logp[NP];
    float gamma;
};

extern __shared__ float smem_raw[];

// ---------------------------------------------------------------------------
// Core matmul: out[32 rows x 256 cols] = A(32 x K) @ B(K x 256).
// A given transposed+swizzled (AT[k][r]); B row-major in gmem, coalesced.
// Warp tile: 8 rows x 128 cols; thread: 8 rows x 4 cols, acc packed over
// row pairs. acc[p*4+i]: rows (rw+2p, rw+2p+1), col c0+i.
// ---------------------------------------------------------------------------
template <int K>
__device__ __forceinline__ void mm_core(const float* __restrict__ AT,
                                        const float* __restrict__ Bg,
                                        int rw, int c0,
                                        unsigned long long acc[16]) {
#pragma unroll
    for (int i = 0; i < 16; i++) acc[i] = 0ull;
#pragma unroll 8
    for (int k = 0; k < K; k++) {
        const int m = (k & 7) << 2;
        const ulonglong2 A0 = *reinterpret_cast<const ulonglong2*>(
            AT + k * 32 + (rw ^ m));            // rows rw..rw+3 (pairs)
        const ulonglong2 A1 = *reinterpret_cast<const ulonglong2*>(
            AT + k * 32 + ((rw + 4) ^ m));      // rows rw+4..rw+7
        const float4 bw = *reinterpret_cast<const float4*>(Bg + k * HID + c0);
        const unsigned long long s0 = splat2(bw.x);
        const unsigned long long s1 = splat2(bw.y);
        const unsigned long long s2 = splat2(bw.z);
        const unsigned long long s3 = splat2(bw.w);
        ffma2(acc[0],  A0.x, s0); ffma2(acc[1],  A0.x, s1);
        ffma2(acc[2],  A0.x, s2); ffma2(acc[3],  A0.x, s3);
        ffma2(acc[4],  A0.y, s0); ffma2(acc[5],  A0.y, s1);
        ffma2(acc[6],  A0.y, s2); ffma2(acc[7],  A0.y, s3);
        ffma2(acc[8],  A1.x, s0); ffma2(acc[9],  A1.x, s1);
        ffma2(acc[10], A1.x, s2); ffma2(acc[11], A1.x, s3);
        ffma2(acc[12], A1.y, s0); ffma2(acc[13], A1.y, s1);
        ffma2(acc[14], A1.y, s2); ffma2(acc[15], A1.y, s3);
    }
}

__global__ void __launch_bounds__(256, 2) svgd_kernel(
    const float* __restrict__ g_obs, const float* __restrict__ g_a,
    const float* __restrict__ g_W1, const float* __restrict__ g_b1,
    const float* __restrict__ g_W2, const float* __restrict__ g_b2,
    const float* __restrict__ g_W3, float* __restrict__ g_out)
{
    Smem* sm = reinterpret_cast<Smem*>(smem_raw);
    const int tid = threadIdx.x;
    const int b = blockIdx.x;
    const int warp = tid >> 5;
    const int lane = tid & 31;
    // matmul tile coords: warp -> (row group, col half); lane -> 4 cols
    const int rw = (warp >> 1) * 8;
    const int c0 = (warp & 1) * 128 + lane * 4;

    // ---- one-time loads --------------------------------------------------
    sm->b1[tid] = g_b1[tid];
    sm->b2[tid] = g_b2[tid];
    sm->W3[tid] = g_W3[tid];
    for (int i = tid; i < NP * DD; i += 256) sm->X[0][i] = g_a[b * NP * DD + i];
    // obs part of inT (k = 0..16), swizzled transposed; built once
    for (int idx = tid; idx < NOBS * 32; idx += 256) {
        const int k = idx >> 5, r = idx & 31;
        sm->inT[atidx(k, r)] = g_obs[b * NP * NOBS + r * NOBS + k];
    }
    if (tid < NP) sm->logp[tid] = 0.0f;
    __syncthreads();

    int cur = 0;
    for (int step = 0; step < NSTEPS; step++) {
        const float* X = sm->X[cur];

        // ---- refresh X part of inT (k = 17..22) -------------------------
        if (tid < DD * 32) {
            const int d = tid >> 5, r = tid & 31;
            sm->inT[atidx(NOBS + d, r)] = X[r * DD + d];
        }
        __syncthreads();

        // ---- z1 = relu(in @ W1 + b1) -> hT (swizzled transposed) --------
        {
            unsigned long long acc[16];
            mm_core<NIN>(sm->inT, g_W1, rw, c0, acc);
#pragma unroll
            for (int i = 0; i < 4; i++) {
                const int c = c0 + i;
                const float bb = sm->b1[c];
                const int sw = (c & 7) << 2;
#pragma unroll
                for (int q = 0; q < 2; q++) {
                    float2 lo = unpack2(acc[(2 * q) * 4 + i]);
                    float2 hi = unpack2(acc[(2 * q + 1) * 4 + i]);
                    float4 v;
                    v.x = fmaxf(lo.x + bb, 0.0f);
                    v.y = fmaxf(lo.y + bb, 0.0f);
                    v.z = fmaxf(hi.x + bb, 0.0f);
                    v.w = fmaxf(hi.y + bb, 0.0f);
                    *reinterpret_cast<float4*>(
                        &sm->hT[c * 32 + ((rw + 4 * q) ^ sw)]) = v;
                }
            }
        }
        __syncthreads();

        // ---- z2 = h1 @ W2 + b2 ; dz2 = (z2>0)*W3 -> dT ------------------
        {
            unsigned long long acc[16];
            mm_core<HID>(sm->hT, g_W2, rw, c0, acc);
#pragma unroll
            for (int i = 0; i < 4; i++) {
                const int c = c0 + i;
                const float bb = sm->b2[c];
                const float w3 = sm->W3[c];
                const int sw = (c & 7) << 2;
#pragma unroll
                for (int q = 0; q < 2; q++) {
                    float2 lo = unpack2(acc[(2 * q) * 4 + i]);
                    float2 hi = unpack2(acc[(2 * q + 1) * 4 + i]);
                    float4 v;
                    v.x = (lo.x + bb > 0.0f) ? w3 : 0.0f;
                    v.y = (lo.y + bb > 0.0f) ? w3 : 0.0f;
                    v.z = (hi.x + bb > 0.0f) ? w3 : 0.0f;
                    v.w = (hi.y + bb > 0.0f) ? w3 : 0.0f;
                    *reinterpret_cast<float4*>(
                        &sm->dT[c * 32 + ((rw + 4 * q) ^ sw)]) = v;
                }
            }
        }
        __syncthreads();

        // ---- dz1 = (h1>0) * (dz2 @ W2^T) -> overwrite hT ----------------
        {
            unsigned long long acc[16];
            mm_core<HID>(sm->dT, g_W2T, rw, c0, acc);
#pragma unroll
            for (int i = 0; i < 4; i++) {
                const int c = c0 + i;
                const int sw = (c & 7) << 2;
#pragma unroll
                for (int q = 0; q < 2; q++) {
                    const int idx = c * 32 + ((rw + 4 * q) ^ sw);
                    float4 mk = *reinterpret_cast<const float4*>(&sm->hT[idx]);
                    float2 lo = unpack2(acc[(2 * q) * 4 + i]);
                    float2 hi = unpack2(acc[(2 * q + 1) * 4 + i]);
                    float4 v;
                    v.x = (mk.x > 0.0f) ? lo.x : 0.0f;
                    v.y = (mk.y > 0.0f) ? lo.y : 0.0f;
                    v.z = (mk.z > 0.0f) ? hi.x : 0.0f;
                    v.w = (mk.w > 0.0f) ? hi.y : 0.0f;
                    *reinterpret_cast<float4*>(&sm->hT[idx]) = v;
                }
            }
        }
        __syncthreads();

        // ---- score = dz1 @ W1[17:23,:]^T  (warp per 4 rows) -------------
        {
            const int swl = (lane & 7) << 2;
            for (int r = warp * 4; r < warp * 4 + 4; r++) {
                float dz[8];
#pragma unroll
                for (int i = 0; i < 8; i++)
                    dz[i] = sm->hT[(lane + 32 * i) * 32 + (r ^ swl)];
                float p[DD];
#pragma unroll
                for (int d = 0; d < DD; d++) {
                    float t = 0.0f;
#pragma unroll
                    for (int i = 0; i < 8; i++)
                        t = fmaf(dz[i], g_W1[(NOBS + d) * HID + lane + 32 * i], t);
#pragma unroll
                    for (int off = 16; off > 0; off >>= 1)
                        t += __shfl_xor_sync(0xFFFFFFFFu, t, off);
                    p[d] = t;
                }
                if (lane == 0) {
#pragma unroll
                    for (int d = 0; d < DD; d++) sm->s[r * DD + d] = p[d];
                }
            }
        }
        __syncthreads();

        // ---- pairwise squared distances + upper-triangle ----------------
        if (tid < 16) sm->sortbuf[496 + tid] = __int_as_float(0x7f800000);
        for (int p = tid; p < NP * NP; p += 256) {
            const int i = p >> 5, j = p & 31;
            float dsq = 0.0f;
#pragma unroll
            for (int d = 0; d < DD; d++) {
                float dx = X[i * DD + d] - X[j * DD + d];
                dsq = fmaf(dx, dx, dsq);
            }
            sm->dsq[p] = dsq;
            if (i < j) {
                const int t = i * NP - ((i * (i + 1)) >> 1) + (j - i - 1);
                sm->sortbuf[t] = dsq;
            }
        }
        __syncthreads();

        // ---- exact median: sort 512 (496 pair values + inf pad).
        // Multiset = 32 diag zeros + each pair twice; element 511 of 1024
        // maps to element (511-32)/2 = 239 of the sorted pairs.
        for (int k = 2; k <= 512; k <<= 1) {
            for (int j = k >> 1; j > 0; j >>= 1) {
                for (int t = tid; t < 512; t += 256) {
                    const int ixj = t ^ j;
                    if (ixj > t) {
                        float v0 = sm->sortbuf[t];
                        float v1 = sm->sortbuf[ixj];
                        const bool up = (t & k) == 0;
                        if ((v0 > v1) == up) {
                            sm->sortbuf[t] = v1;
                            sm->sortbuf[ixj] = v0;
                        }
                    }
                }
                __syncthreads();
            }
        }
        if (tid == 0) {
            const float med = sm->sortbuf[239];
            const float h = med / (2.0f * LOG_NP1);
            sm->gamma = 1.0f / (1e-8f + 2.0f * h);
        }
        __syncthreads();

        // ---- RBF phi / logp update (warp per 4 rows) --------------------
        {
            const float gamma = sm->gamma;
            const int nxt = cur ^ 1;
            for (int i = warp * 4; i < warp * 4 + 4; i++) {
                const int j = lane;
                float dx[DD];
#pragma unroll
                for (int d = 0; d < DD; d++)
                    dx[d] = X[i * DD + d] - X[j * DD + d];
                const float dsq = sm->dsq[i * NP + j];
                const float kap = __expf(-gamma * dsq);
                float red[8];
                float ds = 0.0f;
#pragma unroll
                for (int d = 0; d < DD; d++) {
                    red[d] = kap * (sm->s[j * DD + d] + 2.0f * gamma * dx[d]);
                    ds = fmaf(dx[d], sm->s[j * DD + d], ds);
                }
                red[6] = -2.0f * gamma * kap * ds;                   // line_4
                red[7] = 2.0f * gamma * dsq * kap - (float)DD * kap; // line_5
#pragma unroll
                for (int q = 0; q < 8; q++) {
#pragma unroll
                    for (int off = 16; off > 0; off >>= 1)
                        red[q] += __shfl_xor_sync(0xFFFFFFFFu, red[q], off);
                }
                if (lane == 0) {
#pragma unroll
                    for (int d = 0; d < DD; d++) {
                        const float phi = red[d] * (1.0f / (float)NP);
                        float xn = X[i * DD + d] + LRATE * phi;
                        xn = fminf(fmaxf(xn, -CLIP_LIM), CLIP_LIM);
                        sm->X[nxt][i * DD + d] = xn;
                    }
                    const float l4 = red[6] * (1.0f / (float)NP);
                    const float l5 = -2.0f * gamma * (red[7] * (1.0f / (float)NP));
                    sm->logp[i] -= LRATE * (l4 + l5);
                }
            }
        }
        cur ^= 1;
        __syncthreads();
    }

    // ---- write outputs: a (B*N*D) then logp (B*N) ------------------------
    for (int i = tid; i < NP * DD; i += 256)
        g_out[b * (NP * DD) + i] = sm->X[cur][i];
    if (tid < NP)
        g_out[BATCH * NP * DD + b * NP + tid] = sm->logp[tid];
}

// ---------------------------------------------------------------------------
extern "C" void kernel_launch(void* const* d_in, const int* in_sizes, int n_in,
                              void* d_out, int out_size) {
    const float* obs = (const float*)d_in[0];
    const float* a   = (const float*)d_in[1];
    const float* W1  = (const float*)d_in[2];
    const float* b1  = (const float*)d_in[3];
    const float* W2  = (const float*)d_in[4];
    const float* b2  = (const float*)d_in[5];
    const float* W3  = (const float*)d_in[6];
    // d_in[7] = b3: does not affect outputs — unused.
    float* out = (float*)d_out;

    transposeW2_kernel<<<dim3(8, 8), dim3(32, 8)>>>(W2);

    cudaFuncSetAttribute(svgd_kernel,
                         cudaFuncAttributeMaxDynamicSharedMemorySize,
                         (int)sizeof(Smem));
    svgd_kernel<<<BATCH, 256, sizeof(Smem)>>>(obs, a, W1, b1, W2, b2, W3, out);
}